// round 1
// baseline (speedup 1.0000x reference)
#include <cuda_runtime.h>
#include <math.h>

#define BATCHN  16
#define SEQL    2048
#define INDIM   64
#define HID     256
#define STATEN  256
#define MLPD    1024
#define OUTD    128
#define NLAYERS 4
#define M_TOT   (BATCHN*SEQL)   /* 32768 */
#define CH      128
#define NCH     (SEQL/CH)       /* 16 */

// ---------------- scratch (static device globals; no allocations) ----------
__device__ float g_h  [M_TOT*HID];
__device__ float g_y  [M_TOT*HID];
__device__ float g_bur[M_TOT*STATEN];
__device__ float g_bui[M_TOT*STATEN];
__device__ float g_str[M_TOT*STATEN];
__device__ float g_sti[M_TOT*STATEN];
__device__ float g_z  [M_TOT*MLPD];
__device__ float g_cr [BATCHN*NCH*STATEN];
__device__ float g_ci [BATCHN*NCH*STATEN];

// ---------------- general SGEMM: C[M,N] = epi(A[M,K] @ W[N,K]^T) -----------
// epi: 0 = store acc
//      1 = store acc + bias
//      2 = store gelu(acc + bias)
//      3 = store acc + bias + resid
//      4 = C += alpha * acc
__global__ __launch_bounds__(256)
void sgemm_nt(int M, int N, int K,
              const float* __restrict__ A, const float* __restrict__ W,
              const float* __restrict__ bias, const float* __restrict__ resid,
              float* __restrict__ C, int epi, float alpha)
{
    __shared__ __align__(16) float As[16][64];
    __shared__ __align__(16) float Bs[16][64];

    int tid = threadIdx.x;
    int tx = tid & 15;          // 0..15
    int ty = tid >> 4;          // 0..15
    int row0 = blockIdx.y * 64;
    int col0 = blockIdx.x * 64;

    int lr = tid >> 2;          // 0..63
    int lc = (tid & 3) * 4;     // 0,4,8,12

    const float* Ap = A + (size_t)(row0 + lr) * K + lc;
    const float* Wp = W + (size_t)(col0 + lr) * K + lc;

    float acc[4][4];
    #pragma unroll
    for (int i = 0; i < 4; i++)
        #pragma unroll
        for (int j = 0; j < 4; j++) acc[i][j] = 0.f;

    for (int k0 = 0; k0 < K; k0 += 16) {
        float4 av = *(const float4*)(Ap + k0);
        float4 wv = *(const float4*)(Wp + k0);
        As[lc+0][lr] = av.x; As[lc+1][lr] = av.y; As[lc+2][lr] = av.z; As[lc+3][lr] = av.w;
        Bs[lc+0][lr] = wv.x; Bs[lc+1][lr] = wv.y; Bs[lc+2][lr] = wv.z; Bs[lc+3][lr] = wv.w;
        __syncthreads();
        #pragma unroll
        for (int kk = 0; kk < 16; kk++) {
            float4 a4 = *(const float4*)&As[kk][ty*4];
            float4 b4 = *(const float4*)&Bs[kk][tx*4];
            float a[4] = {a4.x, a4.y, a4.z, a4.w};
            float b[4] = {b4.x, b4.y, b4.z, b4.w};
            #pragma unroll
            for (int i = 0; i < 4; i++)
                #pragma unroll
                for (int j = 0; j < 4; j++)
                    acc[i][j] = fmaf(a[i], b[j], acc[i][j]);
        }
        __syncthreads();
    }

    #pragma unroll
    for (int i = 0; i < 4; i++) {
        int r = row0 + ty*4 + i;
        size_t ro = (size_t)r * N + col0 + tx*4;
        #pragma unroll
        for (int j = 0; j < 4; j++) {
            int c = col0 + tx*4 + j;
            float v = acc[i][j];
            if (epi == 0) {
                C[ro + j] = v;
            } else if (epi == 1) {
                C[ro + j] = v + bias[c];
            } else if (epi == 2) {
                v += bias[c];
                C[ro + j] = 0.5f * v * (1.0f + erff(v * 0.70710678118654752f));
            } else if (epi == 3) {
                C[ro + j] = v + bias[c] + resid[ro + j];
            } else { // 4
                C[ro + j] += alpha * v;
            }
        }
    }
}

// ---------------- LRU scan (chunked) ---------------------------------------
__device__ __forceinline__ void lam_of(const float* nu_log, const float* th_log,
                                       int layer, int s, float& lre, float& lim)
{
    float nu = nu_log[layer*STATEN + s];
    float th = th_log[layer*STATEN + s];
    float mag = expf(-expf(nu));
    float ang = expf(th);
    float sv, cv;
    sincosf(ang, &sv, &cv);
    lre = mag * cv;
    lim = mag * sv;
}

// pass A: local scan within each chunk (reads Bu * gamma, writes local state)
__global__ __launch_bounds__(256)
void scanA(const float* __restrict__ nu_log, const float* __restrict__ th_log,
           const float* __restrict__ gl_log, int layer)
{
    int idx = blockIdx.x * blockDim.x + threadIdx.x;   // B*NCH*STATE = 65536
    int s = idx % STATEN;
    int c = (idx / STATEN) % NCH;
    int b = idx / (STATEN * NCH);
    float lre, lim;
    lam_of(nu_log, th_log, layer, s, lre, lim);
    float ga = expf(gl_log[layer*STATEN + s]);

    size_t base = ((size_t)b * SEQL + (size_t)c * CH) * STATEN + s;
    float sr = 0.f, si = 0.f;
    for (int t = 0; t < CH; t++) {
        size_t o = base + (size_t)t * STATEN;
        float br = g_bur[o] * ga;
        float bi = g_bui[o] * ga;
        float nr = fmaf(lre, sr, fmaf(-lim, si, br));
        float ni = fmaf(lre, si, fmaf( lim, sr, bi));
        sr = nr; si = ni;
        g_str[o] = sr; g_sti[o] = si;
    }
}

// pass B: sequential combine of chunk carries (per b,s; 16 steps)
__global__ __launch_bounds__(256)
void scanB(const float* __restrict__ nu_log, const float* __restrict__ th_log,
           int layer)
{
    int idx = blockIdx.x * blockDim.x + threadIdx.x;   // B*STATE = 4096
    int s = idx % STATEN;
    int b = idx / STATEN;
    float lre, lim;
    lam_of(nu_log, th_log, layer, s, lre, lim);

    // lam^CH with CH = 128 = 2^7  (7 complex squarings)
    float ar = lre, ai = lim;
    #pragma unroll
    for (int q = 0; q < 7; q++) {
        float nr = ar*ar - ai*ai;
        ai = 2.f * ar * ai;
        ar = nr;
    }

    float sr = 0.f, si = 0.f;
    for (int c = 0; c < NCH; c++) {
        g_cr[((size_t)b*NCH + c)*STATEN + s] = sr;
        g_ci[((size_t)b*NCH + c)*STATEN + s] = si;
        size_t o = ((size_t)b * SEQL + (size_t)c * CH + (CH-1)) * STATEN + s;
        float er = g_str[o], ei = g_sti[o];
        float nr = fmaf(ar, sr, fmaf(-ai, si, er));
        float ni = fmaf(ar, si, fmaf( ai, sr, ei));
        sr = nr; si = ni;
    }
}

// pass C: fix-up  state[t0+j] = local[t0+j] + lam^(j+1) * carry_in
__global__ __launch_bounds__(256)
void scanC(const float* __restrict__ nu_log, const float* __restrict__ th_log,
           int layer)
{
    int idx = blockIdx.x * blockDim.x + threadIdx.x;   // B*NCH*STATE
    int s = idx % STATEN;
    int c = (idx / STATEN) % NCH;
    int b = idx / (STATEN * NCH);
    float cr = g_cr[((size_t)b*NCH + c)*STATEN + s];
    float ci = g_ci[((size_t)b*NCH + c)*STATEN + s];
    if (cr == 0.f && ci == 0.f) return;   // chunk 0 (and decayed tails)
    float lre, lim;
    lam_of(nu_log, th_log, layer, s, lre, lim);

    size_t base = ((size_t)b * SEQL + (size_t)c * CH) * STATEN + s;
    for (int t = 0; t < CH; t++) {
        float nr = lre*cr - lim*ci;
        ci = fmaf(lre, ci, lim*cr);
        cr = nr;
        size_t o = base + (size_t)t * STATEN;
        g_str[o] += cr;
        g_sti[o] += ci;
    }
}

// ---------------- y += D[h] * h_in ------------------------------------------
__global__ __launch_bounds__(256)
void add_Dx(const float* __restrict__ Dv, int n)
{
    int i = blockIdx.x * blockDim.x + threadIdx.x;
    if (i < n) g_y[i] = fmaf(Dv[i % HID], g_h[i], g_y[i]);
}

// ---------------- driver ----------------------------------------------------
extern "C" void kernel_launch(void* const* d_in, const int* in_sizes, int n_in,
                              void* d_out, int out_size)
{
    (void)in_sizes; (void)n_in; (void)out_size;
    const float* x    = (const float*)d_in[0];
    const float* embW = (const float*)d_in[1];
    const float* embb = (const float*)d_in[2];
    const float* nu   = (const float*)d_in[3];
    const float* th   = (const float*)d_in[4];
    const float* gl   = (const float*)d_in[5];
    const float* Bre  = (const float*)d_in[6];
    const float* Bim  = (const float*)d_in[7];
    const float* Cre  = (const float*)d_in[8];
    const float* Cim  = (const float*)d_in[9];
    const float* Dv   = (const float*)d_in[10];
    const float* Wh   = (const float*)d_in[11];
    const float* bh   = (const float*)d_in[12];
    const float* Wo   = (const float*)d_in[13];
    const float* bo   = (const float*)d_in[14];
    const float* outW = (const float*)d_in[15];
    const float* outb = (const float*)d_in[16];
    float* out = (float*)d_out;

    float *h, *y, *bur, *bui, *str, *sti, *z;
    cudaGetSymbolAddress((void**)&h,   g_h);
    cudaGetSymbolAddress((void**)&y,   g_y);
    cudaGetSymbolAddress((void**)&bur, g_bur);
    cudaGetSymbolAddress((void**)&bui, g_bui);
    cudaGetSymbolAddress((void**)&str, g_str);
    cudaGetSymbolAddress((void**)&sti, g_sti);
    cudaGetSymbolAddress((void**)&z,   g_z);

    dim3 tb(256);
    const int MR = M_TOT / 64;   // 512 row-blocks

    // embedding: h = x @ embW^T + embb
    sgemm_nt<<<dim3(HID/64, MR), tb>>>(M_TOT, HID, INDIM, x, embW, embb, nullptr, h, 1, 1.f);

    for (int l = 0; l < NLAYERS; l++) {
        const float* Brel = Bre + (size_t)l*STATEN*HID;
        const float* Biml = Bim + (size_t)l*STATEN*HID;
        const float* Crel = Cre + (size_t)l*HID*STATEN;
        const float* Ciml = Cim + (size_t)l*HID*STATEN;

        // Bu = h @ B^T (complex; gamma scale applied in scanA)
        sgemm_nt<<<dim3(STATEN/64, MR), tb>>>(M_TOT, STATEN, HID, h, Brel, nullptr, nullptr, bur, 0, 1.f);
        sgemm_nt<<<dim3(STATEN/64, MR), tb>>>(M_TOT, STATEN, HID, h, Biml, nullptr, nullptr, bui, 0, 1.f);

        // chunked complex scan
        scanA<<<(BATCHN*NCH*STATEN)/256, tb>>>(nu, th, gl, l);
        scanB<<<(BATCHN*STATEN)/256,      tb>>>(nu, th, l);
        scanC<<<(BATCHN*NCH*STATEN)/256, tb>>>(nu, th, l);

        // y = Re(states @ C^T) = st_re@Cre^T - st_im@Cim^T ; then y += D*h
        sgemm_nt<<<dim3(HID/64, MR), tb>>>(M_TOT, HID, STATEN, str, Crel, nullptr, nullptr, y, 0,  1.f);
        sgemm_nt<<<dim3(HID/64, MR), tb>>>(M_TOT, HID, STATEN, sti, Ciml, nullptr, nullptr, y, 4, -1.f);
        add_Dx<<<(M_TOT*HID)/256, tb>>>(Dv + (size_t)l*HID, M_TOT*HID);

        // MLP: z = gelu(y@Wh^T + bh) ; h = z@Wo^T + bo + y
        sgemm_nt<<<dim3(MLPD/64, MR), tb>>>(M_TOT, MLPD, HID, y, Wh + (size_t)l*MLPD*HID,
                                            bh + (size_t)l*MLPD, nullptr, z, 2, 1.f);
        sgemm_nt<<<dim3(HID/64, MR), tb>>>(M_TOT, HID, MLPD, z, Wo + (size_t)l*HID*MLPD,
                                           bo + (size_t)l*HID, y, h, 3, 1.f);
    }

    // out = h @ outW^T + outb
    sgemm_nt<<<dim3(OUTD/64, MR), tb>>>(M_TOT, OUTD, HID, h, outW, outb, nullptr, out, 1, 1.f);
}

// round 2
// speedup vs baseline: 2.5256x; 2.5256x over previous
#include <cuda_runtime.h>
#include <math.h>
#include <stdint.h>

#define BATCHN  16
#define SEQL    2048
#define INDIM   64
#define HID     256
#define STATEN  256
#define MLPD    1024
#define OUTD    128
#define NLAYERS 4
#define M_TOT   (BATCHN*SEQL)   /* 32768 */
#define CH      64
#define NCH     (SEQL/CH)       /* 32 */
#define LOG2CH  6

// ---------------- scratch (static device globals; no allocations) ----------
__device__ float g_h  [M_TOT*HID];
__device__ float g_y  [M_TOT*HID];
__device__ float g_bur[M_TOT*STATEN];
__device__ float g_bui[M_TOT*STATEN];
__device__ float g_str[M_TOT*STATEN];
__device__ float g_sti[M_TOT*STATEN];
__device__ float g_z  [M_TOT*MLPD];
__device__ float g_cr [BATCHN*NCH*STATEN];
__device__ float g_ci [BATCHN*NCH*STATEN];

// ==================== TF32 tensor-core GEMM =================================
// C[M,N] = epi(A[M,K] @ W[N,K]^T)
// epi: 0 = store
//      1 = store + bias
//      2 = store gelu(acc + bias)
//      3 = store acc + bias + resid
//      4 = C += alpha*acc
//      5 = C += alpha*acc + bias[c]*resid   (bias slot carries D vector)
#define BM 128
#define BN 128
#define BK 16
#define ASTR 20                      /* padded row stride in floats */
#define STG  (BM*ASTR*4)             /* stage stride in bytes       */

__device__ __forceinline__ uint32_t f2tf32(float x){
    uint32_t r; asm("cvt.rna.tf32.f32 %0, %1;" : "=r"(r) : "f"(x)); return r;
}
__device__ __forceinline__ void cp16(uint32_t dst, const float* src){
    asm volatile("cp.async.ca.shared.global [%0], [%1], 16;\n" :: "r"(dst), "l"(src));
}
__device__ __forceinline__ void mma_tf32(float* c, const uint32_t* a, const uint32_t* b){
    asm volatile("mma.sync.aligned.m16n8k8.row.col.f32.tf32.tf32.f32 "
        "{%0,%1,%2,%3}, {%4,%5,%6,%7}, {%8,%9}, {%0,%1,%2,%3};"
        : "+f"(c[0]), "+f"(c[1]), "+f"(c[2]), "+f"(c[3])
        : "r"(a[0]), "r"(a[1]), "r"(a[2]), "r"(a[3]), "r"(b[0]), "r"(b[1]));
}

__global__ __launch_bounds__(256,2)
void tgemm_nt(int M, int N, int K,
              const float* __restrict__ A, const float* __restrict__ W,
              const float* __restrict__ bias, const float* __restrict__ resid,
              float* __restrict__ C, int epi, float alpha)
{
    __shared__ __align__(16) float As[2][BM*ASTR];
    __shared__ __align__(16) float Bs[2][BN*ASTR];

    int tid  = threadIdx.x;
    int lane = tid & 31;
    int wid  = tid >> 5;
    int gr   = lane >> 2;       // 0..7
    int ct   = lane & 3;        // 0..3
    int wm   = (wid >> 2) * 64; // 0 or 64
    int wn   = (wid & 3) * 32;  // 0,32,64,96
    int row0 = blockIdx.y * BM;
    int col0 = blockIdx.x * BN;

    // global->smem mapping: each thread loads 2 contiguous float4 (32B) per tile
    int lrow = tid >> 1;            // 0..127
    int loff = (tid & 1) * 8;       // 0 or 8 floats
    const float* Ag = A + (size_t)(row0 + lrow) * K + loff;
    const float* Wg = W + (size_t)(col0 + lrow) * K + loff;
    uint32_t sA = (uint32_t)__cvta_generic_to_shared(&As[0][lrow*ASTR + loff]);
    uint32_t sB = (uint32_t)__cvta_generic_to_shared(&Bs[0][lrow*ASTR + loff]);

    float acc[4][4][4];
    #pragma unroll
    for (int i=0;i<4;i++)
        #pragma unroll
        for (int j=0;j<4;j++)
            #pragma unroll
            for (int q=0;q<4;q++) acc[i][j][q] = 0.f;

    int nk = K / BK;

    // prologue: stage 0
    cp16(sA,      Ag);  cp16(sA + 16, Ag + 4);
    cp16(sB,      Wg);  cp16(sB + 16, Wg + 4);
    asm volatile("cp.async.commit_group;\n");

    for (int kt = 0; kt < nk; kt++) {
        int st = kt & 1;
        if (kt + 1 < nk) {
            int ns = st ^ 1;
            int k0 = (kt + 1) * BK;
            cp16(sA + ns*STG,      Ag + k0);  cp16(sA + ns*STG + 16, Ag + k0 + 4);
            cp16(sB + ns*STG,      Wg + k0);  cp16(sB + ns*STG + 16, Wg + k0 + 4);
            asm volatile("cp.async.commit_group;\n");
            asm volatile("cp.async.wait_group 1;\n");
        } else {
            asm volatile("cp.async.wait_group 0;\n");
        }
        __syncthreads();

        const float* Asm = &As[st][0];
        const float* Bsm = &Bs[st][0];
        #pragma unroll
        for (int ks = 0; ks < 2; ks++) {
            int kk = ks*8 + ct;
            uint32_t ua[4][4], ub[4][2];
            #pragma unroll
            for (int mt = 0; mt < 4; mt++) {
                int r = wm + mt*16 + gr;
                ua[mt][0] = f2tf32(Asm[ r      *ASTR + kk    ]);
                ua[mt][1] = f2tf32(Asm[(r + 8)*ASTR + kk    ]);
                ua[mt][2] = f2tf32(Asm[ r      *ASTR + kk + 4]);
                ua[mt][3] = f2tf32(Asm[(r + 8)*ASTR + kk + 4]);
            }
            #pragma unroll
            for (int nt = 0; nt < 4; nt++) {
                int n = wn + nt*8 + gr;
                ub[nt][0] = f2tf32(Bsm[n*ASTR + kk    ]);
                ub[nt][1] = f2tf32(Bsm[n*ASTR + kk + 4]);
            }
            #pragma unroll
            for (int mt = 0; mt < 4; mt++)
                #pragma unroll
                for (int nt = 0; nt < 4; nt++)
                    mma_tf32(acc[mt][nt], ua[mt], ub[nt]);
        }
        __syncthreads();
    }

    // ---------------- epilogue ----------------
    #pragma unroll
    for (int mt = 0; mt < 4; mt++) {
        #pragma unroll
        for (int half = 0; half < 2; half++) {
            int r = row0 + wm + mt*16 + gr + half*8;
            size_t ro = (size_t)r * N;
            #pragma unroll
            for (int nt = 0; nt < 4; nt++) {
                int cc = col0 + wn + nt*8 + ct*2;
                float v0 = acc[mt][nt][half*2 + 0];
                float v1 = acc[mt][nt][half*2 + 1];
                if (epi == 0) {
                    C[ro + cc]     = v0;
                    C[ro + cc + 1] = v1;
                } else if (epi == 1) {
                    C[ro + cc]     = v0 + bias[cc];
                    C[ro + cc + 1] = v1 + bias[cc + 1];
                } else if (epi == 2) {
                    float t0 = v0 + bias[cc];
                    float t1 = v1 + bias[cc + 1];
                    C[ro + cc]     = 0.5f * t0 * (1.0f + erff(t0 * 0.70710678118654752f));
                    C[ro + cc + 1] = 0.5f * t1 * (1.0f + erff(t1 * 0.70710678118654752f));
                } else if (epi == 3) {
                    C[ro + cc]     = v0 + bias[cc]     + resid[ro + cc];
                    C[ro + cc + 1] = v1 + bias[cc + 1] + resid[ro + cc + 1];
                } else if (epi == 4) {
                    C[ro + cc]     += alpha * v0;
                    C[ro + cc + 1] += alpha * v1;
                } else { // 5: C += alpha*v + D[c]*resid
                    C[ro + cc]     += alpha * v0 + bias[cc]     * resid[ro + cc];
                    C[ro + cc + 1] += alpha * v1 + bias[cc + 1] * resid[ro + cc + 1];
                }
            }
        }
    }
}

// ==================== LRU scan (chunked, fp32) ==============================
__device__ __forceinline__ void lam_of(const float* nu_log, const float* th_log,
                                       int layer, int s, float& lre, float& lim)
{
    float nu = nu_log[layer*STATEN + s];
    float th = th_log[layer*STATEN + s];
    float mag = expf(-expf(nu));
    float ang = expf(th);
    float sv, cv;
    sincosf(ang, &sv, &cv);
    lre = mag * cv;
    lim = mag * sv;
}

__global__ __launch_bounds__(256)
void scanA(const float* __restrict__ nu_log, const float* __restrict__ th_log,
           const float* __restrict__ gl_log, int layer)
{
    int idx = blockIdx.x * blockDim.x + threadIdx.x;   // B*NCH*STATE
    int s = idx % STATEN;
    int c = (idx / STATEN) % NCH;
    int b = idx / (STATEN * NCH);
    float lre, lim;
    lam_of(nu_log, th_log, layer, s, lre, lim);
    float ga = expf(gl_log[layer*STATEN + s]);

    size_t base = ((size_t)b * SEQL + (size_t)c * CH) * STATEN + s;
    float sr = 0.f, si = 0.f;
    for (int t = 0; t < CH; t++) {
        size_t o = base + (size_t)t * STATEN;
        float br = g_bur[o] * ga;
        float bi = g_bui[o] * ga;
        float nr = fmaf(lre, sr, fmaf(-lim, si, br));
        float ni = fmaf(lre, si, fmaf( lim, sr, bi));
        sr = nr; si = ni;
        g_str[o] = sr; g_sti[o] = si;
    }
}

__global__ __launch_bounds__(256)
void scanB(const float* __restrict__ nu_log, const float* __restrict__ th_log,
           int layer)
{
    int idx = blockIdx.x * blockDim.x + threadIdx.x;   // B*STATE
    int s = idx % STATEN;
    int b = idx / STATEN;
    float lre, lim;
    lam_of(nu_log, th_log, layer, s, lre, lim);

    float ar = lre, ai = lim;          // lam^CH via LOG2CH squarings
    #pragma unroll
    for (int q = 0; q < LOG2CH; q++) {
        float nr = ar*ar - ai*ai;
        ai = 2.f * ar * ai;
        ar = nr;
    }

    float sr = 0.f, si = 0.f;
    for (int c = 0; c < NCH; c++) {
        g_cr[((size_t)b*NCH + c)*STATEN + s] = sr;
        g_ci[((size_t)b*NCH + c)*STATEN + s] = si;
        size_t o = ((size_t)b * SEQL + (size_t)c * CH + (CH-1)) * STATEN + s;
        float er = g_str[o], ei = g_sti[o];
        float nr = fmaf(ar, sr, fmaf(-ai, si, er));
        float ni = fmaf(ar, si, fmaf( ai, sr, ei));
        sr = nr; si = ni;
    }
}

__global__ __launch_bounds__(256)
void scanC(const float* __restrict__ nu_log, const float* __restrict__ th_log,
           int layer)
{
    int idx = blockIdx.x * blockDim.x + threadIdx.x;   // B*NCH*STATE
    int s = idx % STATEN;
    int c = (idx / STATEN) % NCH;
    int b = idx / (STATEN * NCH);
    float cr = g_cr[((size_t)b*NCH + c)*STATEN + s];
    float ci = g_ci[((size_t)b*NCH + c)*STATEN + s];
    if (cr == 0.f && ci == 0.f) return;
    float lre, lim;
    lam_of(nu_log, th_log, layer, s, lre, lim);

    size_t base = ((size_t)b * SEQL + (size_t)c * CH) * STATEN + s;
    for (int t = 0; t < CH; t++) {
        float nr = lre*cr - lim*ci;
        ci = fmaf(lre, ci, lim*cr);
        cr = nr;
        size_t o = base + (size_t)t * STATEN;
        g_str[o] += cr;
        g_sti[o] += ci;
    }
}

// ==================== driver ================================================
extern "C" void kernel_launch(void* const* d_in, const int* in_sizes, int n_in,
                              void* d_out, int out_size)
{
    (void)in_sizes; (void)n_in; (void)out_size;
    const float* x    = (const float*)d_in[0];
    const float* embW = (const float*)d_in[1];
    const float* embb = (const float*)d_in[2];
    const float* nu   = (const float*)d_in[3];
    const float* th   = (const float*)d_in[4];
    const float* gl   = (const float*)d_in[5];
    const float* Bre  = (const float*)d_in[6];
    const float* Bim  = (const float*)d_in[7];
    const float* Cre  = (const float*)d_in[8];
    const float* Cim  = (const float*)d_in[9];
    const float* Dv   = (const float*)d_in[10];
    const float* Wh   = (const float*)d_in[11];
    const float* bh   = (const float*)d_in[12];
    const float* Wo   = (const float*)d_in[13];
    const float* bo   = (const float*)d_in[14];
    const float* outW = (const float*)d_in[15];
    const float* outb = (const float*)d_in[16];
    float* out = (float*)d_out;

    float *h, *y, *bur, *bui, *str, *sti, *z;
    cudaGetSymbolAddress((void**)&h,   g_h);
    cudaGetSymbolAddress((void**)&y,   g_y);
    cudaGetSymbolAddress((void**)&bur, g_bur);
    cudaGetSymbolAddress((void**)&bui, g_bui);
    cudaGetSymbolAddress((void**)&str, g_str);
    cudaGetSymbolAddress((void**)&sti, g_sti);
    cudaGetSymbolAddress((void**)&z,   g_z);

    dim3 tb(256);
    const int MB = M_TOT / BM;   // 256 row-blocks

    // embedding: h = x @ embW^T + embb
    tgemm_nt<<<dim3(HID/BN, MB), tb>>>(M_TOT, HID, INDIM, x, embW, embb, nullptr, h, 1, 1.f);

    for (int l = 0; l < NLAYERS; l++) {
        const float* Brel = Bre + (size_t)l*STATEN*HID;
        const float* Biml = Bim + (size_t)l*STATEN*HID;
        const float* Crel = Cre + (size_t)l*HID*STATEN;
        const float* Ciml = Cim + (size_t)l*HID*STATEN;

        // Bu = h @ B^T (complex; gamma applied in scanA)
        tgemm_nt<<<dim3(STATEN/BN, MB), tb>>>(M_TOT, STATEN, HID, h, Brel, nullptr, nullptr, bur, 0, 1.f);
        tgemm_nt<<<dim3(STATEN/BN, MB), tb>>>(M_TOT, STATEN, HID, h, Biml, nullptr, nullptr, bui, 0, 1.f);

        // chunked complex scan
        scanA<<<(BATCHN*NCH*STATEN)/256, tb>>>(nu, th, gl, l);
        scanB<<<(BATCHN*STATEN + 255)/256, tb>>>(nu, th, l);
        scanC<<<(BATCHN*NCH*STATEN)/256, tb>>>(nu, th, l);

        // y = Re(states @ C^T) + D*h
        tgemm_nt<<<dim3(HID/BN, MB), tb>>>(M_TOT, HID, STATEN, str, Crel, nullptr, nullptr, y, 0, 1.f);
        tgemm_nt<<<dim3(HID/BN, MB), tb>>>(M_TOT, HID, STATEN, sti, Ciml,
                                           Dv + (size_t)l*HID, h, y, 5, -1.f);

        // MLP: z = gelu(y@Wh^T + bh) ; h = z@Wo^T + bo + y
        tgemm_nt<<<dim3(MLPD/BN, MB), tb>>>(M_TOT, MLPD, HID, y, Wh + (size_t)l*MLPD*HID,
                                            bh + (size_t)l*MLPD, nullptr, z, 2, 1.f);
        tgemm_nt<<<dim3(HID/BN, MB), tb>>>(M_TOT, HID, MLPD, z, Wo + (size_t)l*HID*MLPD,
                                           bo + (size_t)l*HID, y, h, 3, 1.f);
    }

    // out = h @ outW^T + outb
    tgemm_nt<<<dim3(OUTD/BN, MB), tb>>>(M_TOT, OUTD, HID, h, outW, outb, nullptr, out, 1, 1.f);
}

// round 3
// speedup vs baseline: 2.7298x; 1.0809x over previous
#include <cuda_runtime.h>
#include <math.h>
#include <stdint.h>

#define BATCHN  16
#define SEQL    2048
#define INDIM   64
#define HID     256
#define STATEN  256
#define MLPD    1024
#define OUTD    128
#define NLAYERS 4
#define M_TOT   (BATCHN*SEQL)   /* 32768 */
#define CH      64
#define NCH     (SEQL/CH)       /* 32 */
#define LOG2CH  6
#define S2      (2*STATEN)      /* 512 */

// ---------------- scratch (static device globals) ---------------------------
__device__ float g_h  [M_TOT*HID];
__device__ float g_y  [M_TOT*HID];
__device__ float g_bu [M_TOT*S2];       // [M, 512]: cols 0-255 re, 256-511 im
__device__ float g_st [M_TOT*S2];
__device__ float g_z  [M_TOT*MLPD];
__device__ float g_cr [BATCHN*NCH*STATEN];
__device__ float g_ci [BATCHN*NCH*STATEN];
// pre-rounded (tf32-valued) weights / input
__device__ float g_xr  [M_TOT*INDIM];
__device__ float g_wE  [HID*INDIM];
__device__ float g_wB  [NLAYERS*S2*HID];     // [l][512][256] : Bre stacked on Bim
__device__ float g_wC  [NLAYERS*HID*S2];     // [l][256][512] : [Cre | -Cim]
__device__ float g_wH  [NLAYERS*MLPD*HID];
__device__ float g_wO  [NLAYERS*HID*MLPD];
__device__ float g_wOut[OUTD*HID];

__device__ __forceinline__ float rtf(float x){
    uint32_t r; asm("cvt.rna.tf32.f32 %0, %1;" : "=r"(r) : "f"(x));
    return __uint_as_float(r);
}

// ==================== TF32 tensor-core GEMM =================================
// C[M,N] = epi(A[M,K] @ W[N,K]^T)   (A, W already tf32-valued)
// epi: 0 = store raw
//      1 = store acc + bias            (final output, no rounding)
//      2 = store rtf(gelu(acc+bias))
//      3 = store rtf(acc+bias+resid)
//      6 = store rtf(acc+bias)
//      7 = store rtf(acc + bias[c]*resid)   (bias slot carries D vector)
#define BM 128
#define BN 128
#define BK 16
#define ASTR 20
#define STG  (BM*ASTR*4)

__device__ __forceinline__ void cp16(uint32_t dst, const float* src){
    asm volatile("cp.async.ca.shared.global [%0], [%1], 16;\n" :: "r"(dst), "l"(src));
}
__device__ __forceinline__ void mma_tf32(float* c, const uint32_t* a, const uint32_t* b){
    asm volatile("mma.sync.aligned.m16n8k8.row.col.f32.tf32.tf32.f32 "
        "{%0,%1,%2,%3}, {%4,%5,%6,%7}, {%8,%9}, {%0,%1,%2,%3};"
        : "+f"(c[0]), "+f"(c[1]), "+f"(c[2]), "+f"(c[3])
        : "r"(a[0]), "r"(a[1]), "r"(a[2]), "r"(a[3]), "r"(b[0]), "r"(b[1]));
}

__global__ __launch_bounds__(256,2)
void tgemm_nt(int M, int N, int K,
              const float* __restrict__ A, const float* __restrict__ W,
              const float* __restrict__ bias, const float* __restrict__ resid,
              float* __restrict__ C, int epi)
{
    __shared__ __align__(16) float As[2][BM*ASTR];
    __shared__ __align__(16) float Bs[2][BN*ASTR];

    int tid  = threadIdx.x;
    int lane = tid & 31;
    int wid  = tid >> 5;
    int gr   = lane >> 2;       // 0..7
    int ct   = lane & 3;        // 0..3
    int wm   = (wid >> 2) * 64;
    int wn   = (wid & 3) * 32;
    int row0 = blockIdx.y * BM;
    int col0 = blockIdx.x * BN;

    int lrow = tid >> 1;
    int loff = (tid & 1) * 8;
    const float* Ag = A + (size_t)(row0 + lrow) * K + loff;
    const float* Wg = W + (size_t)(col0 + lrow) * K + loff;
    uint32_t sA = (uint32_t)__cvta_generic_to_shared(&As[0][lrow*ASTR + loff]);
    uint32_t sB = (uint32_t)__cvta_generic_to_shared(&Bs[0][lrow*ASTR + loff]);

    float acc[4][4][4];
    #pragma unroll
    for (int i=0;i<4;i++)
        #pragma unroll
        for (int j=0;j<4;j++)
            #pragma unroll
            for (int q=0;q<4;q++) acc[i][j][q] = 0.f;

    int nk = K / BK;

    cp16(sA,      Ag);  cp16(sA + 16, Ag + 4);
    cp16(sB,      Wg);  cp16(sB + 16, Wg + 4);
    asm volatile("cp.async.commit_group;\n");

    for (int kt = 0; kt < nk; kt++) {
        int st = kt & 1;
        if (kt + 1 < nk) {
            int ns = st ^ 1;
            int k0 = (kt + 1) * BK;
            cp16(sA + ns*STG,      Ag + k0);  cp16(sA + ns*STG + 16, Ag + k0 + 4);
            cp16(sB + ns*STG,      Wg + k0);  cp16(sB + ns*STG + 16, Wg + k0 + 4);
            asm volatile("cp.async.commit_group;\n");
            asm volatile("cp.async.wait_group 1;\n");
        } else {
            asm volatile("cp.async.wait_group 0;\n");
        }
        __syncthreads();

        const uint32_t* Asm = (const uint32_t*)&As[st][0];
        const uint32_t* Bsm = (const uint32_t*)&Bs[st][0];
        #pragma unroll
        for (int ks = 0; ks < 2; ks++) {
            int kk = ks*8 + ct;
            uint32_t ua[4][4], ub[4][2];
            #pragma unroll
            for (int mt = 0; mt < 4; mt++) {
                int r = wm + mt*16 + gr;
                ua[mt][0] = Asm[ r      *ASTR + kk    ];
                ua[mt][1] = Asm[(r + 8)*ASTR + kk    ];
                ua[mt][2] = Asm[ r      *ASTR + kk + 4];
                ua[mt][3] = Asm[(r + 8)*ASTR + kk + 4];
            }
            #pragma unroll
            for (int nt = 0; nt < 4; nt++) {
                int n = wn + nt*8 + gr;
                ub[nt][0] = Bsm[n*ASTR + kk    ];
                ub[nt][1] = Bsm[n*ASTR + kk + 4];
            }
            #pragma unroll
            for (int mt = 0; mt < 4; mt++)
                #pragma unroll
                for (int nt = 0; nt < 4; nt++)
                    mma_tf32(acc[mt][nt], ua[mt], ub[nt]);
        }
        __syncthreads();
    }

    #pragma unroll
    for (int mt = 0; mt < 4; mt++) {
        #pragma unroll
        for (int half = 0; half < 2; half++) {
            int r = row0 + wm + mt*16 + gr + half*8;
            size_t ro = (size_t)r * N;
            #pragma unroll
            for (int nt = 0; nt < 4; nt++) {
                int cc = col0 + wn + nt*8 + ct*2;
                float v0 = acc[mt][nt][half*2 + 0];
                float v1 = acc[mt][nt][half*2 + 1];
                if (epi == 0) {
                    C[ro + cc]     = v0;
                    C[ro + cc + 1] = v1;
                } else if (epi == 1) {
                    C[ro + cc]     = v0 + bias[cc];
                    C[ro + cc + 1] = v1 + bias[cc + 1];
                } else if (epi == 2) {
                    float t0 = v0 + bias[cc];
                    float t1 = v1 + bias[cc + 1];
                    C[ro + cc]     = rtf(0.5f * t0 * (1.0f + erff(t0 * 0.70710678118654752f)));
                    C[ro + cc + 1] = rtf(0.5f * t1 * (1.0f + erff(t1 * 0.70710678118654752f)));
                } else if (epi == 3) {
                    C[ro + cc]     = rtf(v0 + bias[cc]     + resid[ro + cc]);
                    C[ro + cc + 1] = rtf(v1 + bias[cc + 1] + resid[ro + cc + 1]);
                } else if (epi == 6) {
                    C[ro + cc]     = rtf(v0 + bias[cc]);
                    C[ro + cc + 1] = rtf(v1 + bias[cc + 1]);
                } else { // 7
                    C[ro + cc]     = rtf(v0 + bias[cc]     * resid[ro + cc]);
                    C[ro + cc + 1] = rtf(v1 + bias[cc + 1] * resid[ro + cc + 1]);
                }
            }
        }
    }
}

// ==================== weight prep (tf32 rounding / concat) ==================
__global__ void round_copy(float* __restrict__ dst, const float* __restrict__ src, int n)
{
    int i = blockIdx.x * blockDim.x + threadIdx.x;
    if (i < n) dst[i] = rtf(src[i]);
}
// Bcat[l][row][k]: row<256 -> Bre[l][row][k], else Bim[l][row-256][k]
__global__ void build_bcat(const float* __restrict__ Bre, const float* __restrict__ Bim)
{
    int i = blockIdx.x * blockDim.x + threadIdx.x;     // NLAYERS*512*256
    int k = i & (HID-1);
    int row = (i >> 8) & (S2-1);
    int l = i >> 17;
    float v = (row < STATEN) ? Bre[((size_t)l*STATEN + row)*HID + k]
                             : Bim[((size_t)l*STATEN + row - STATEN)*HID + k];
    g_wB[i] = rtf(v);
}
// Ccat[l][h][k]: k<256 -> Cre[l][h][k], else -Cim[l][h][k-256]
__global__ void build_ccat(const float* __restrict__ Cre, const float* __restrict__ Cim)
{
    int i = blockIdx.x * blockDim.x + threadIdx.x;     // NLAYERS*256*512
    int k = i & (S2-1);
    int hh = (i >> 9) & (HID-1);
    int l = i >> 17;
    float v = (k < STATEN) ?  Cre[((size_t)l*HID + hh)*STATEN + k]
                           : -Cim[((size_t)l*HID + hh)*STATEN + k - STATEN];
    g_wC[i] = rtf(v);
}

// ==================== LRU scan (chunked, fp32) ==============================
__device__ __forceinline__ void lam_of(const float* nu_log, const float* th_log,
                                       int layer, int s, float& lre, float& lim)
{
    float nu = nu_log[layer*STATEN + s];
    float th = th_log[layer*STATEN + s];
    float mag = expf(-expf(nu));
    float ang = expf(th);
    float sv, cv;
    sincosf(ang, &sv, &cv);
    lre = mag * cv;
    lim = mag * sv;
}

__global__ __launch_bounds__(256)
void scanA(const float* __restrict__ nu_log, const float* __restrict__ th_log,
           const float* __restrict__ gl_log, int layer)
{
    int idx = blockIdx.x * blockDim.x + threadIdx.x;   // B*NCH*STATE
    int s = idx % STATEN;
    int c = (idx / STATEN) % NCH;
    int b = idx / (STATEN * NCH);
    float lre, lim;
    lam_of(nu_log, th_log, layer, s, lre, lim);
    float ga = expf(gl_log[layer*STATEN + s]);

    size_t base = ((size_t)b * SEQL + (size_t)c * CH) * S2 + s;
    float sr = 0.f, si = 0.f;
    for (int t = 0; t < CH; t++) {
        size_t o = base + (size_t)t * S2;
        float br = g_bu[o]          * ga;
        float bi = g_bu[o + STATEN] * ga;
        float nr = fmaf(lre, sr, fmaf(-lim, si, br));
        float ni = fmaf(lre, si, fmaf( lim, sr, bi));
        sr = nr; si = ni;
        g_st[o] = sr; g_st[o + STATEN] = si;
    }
}

__global__ __launch_bounds__(256)
void scanB(const float* __restrict__ nu_log, const float* __restrict__ th_log,
           int layer)
{
    int idx = blockIdx.x * blockDim.x + threadIdx.x;   // B*STATE
    int s = idx % STATEN;
    int b = idx / STATEN;
    float lre, lim;
    lam_of(nu_log, th_log, layer, s, lre, lim);

    float ar = lre, ai = lim;
    #pragma unroll
    for (int q = 0; q < LOG2CH; q++) {
        float nr = ar*ar - ai*ai;
        ai = 2.f * ar * ai;
        ar = nr;
    }

    float sr = 0.f, si = 0.f;
    for (int c = 0; c < NCH; c++) {
        g_cr[((size_t)b*NCH + c)*STATEN + s] = sr;
        g_ci[((size_t)b*NCH + c)*STATEN + s] = si;
        size_t o = ((size_t)b * SEQL + (size_t)c * CH + (CH-1)) * S2 + s;
        float er = g_st[o], ei = g_st[o + STATEN];
        float nr = fmaf(ar, sr, fmaf(-ai, si, er));
        float ni = fmaf(ar, si, fmaf( ai, sr, ei));
        sr = nr; si = ni;
    }
}

__global__ __launch_bounds__(256)
void scanC(const float* __restrict__ nu_log, const float* __restrict__ th_log,
           int layer)
{
    int idx = blockIdx.x * blockDim.x + threadIdx.x;   // B*NCH*STATE
    int s = idx % STATEN;
    int c = (idx / STATEN) % NCH;
    int b = idx / (STATEN * NCH);
    float cr = g_cr[((size_t)b*NCH + c)*STATEN + s];
    float ci = g_ci[((size_t)b*NCH + c)*STATEN + s];
    float lre, lim;
    lam_of(nu_log, th_log, layer, s, lre, lim);

    size_t base = ((size_t)b * SEQL + (size_t)c * CH) * S2 + s;
    for (int t = 0; t < CH; t++) {
        float nr = lre*cr - lim*ci;
        ci = fmaf(lre, ci, lim*cr);
        cr = nr;
        size_t o = base + (size_t)t * S2;
        g_st[o]          = rtf(g_st[o]          + cr);
        g_st[o + STATEN] = rtf(g_st[o + STATEN] + ci);
    }
}

// ==================== driver ================================================
extern "C" void kernel_launch(void* const* d_in, const int* in_sizes, int n_in,
                              void* d_out, int out_size)
{
    (void)in_sizes; (void)n_in; (void)out_size;
    const float* x    = (const float*)d_in[0];
    const float* embW = (const float*)d_in[1];
    const float* embb = (const float*)d_in[2];
    const float* nu   = (const float*)d_in[3];
    const float* th   = (const float*)d_in[4];
    const float* gl   = (const float*)d_in[5];
    const float* Bre  = (const float*)d_in[6];
    const float* Bim  = (const float*)d_in[7];
    const float* Cre  = (const float*)d_in[8];
    const float* Cim  = (const float*)d_in[9];
    const float* Dv   = (const float*)d_in[10];
    const float* Wh   = (const float*)d_in[11];
    const float* bh   = (const float*)d_in[12];
    const float* Wo   = (const float*)d_in[13];
    const float* bo   = (const float*)d_in[14];
    const float* outW = (const float*)d_in[15];
    const float* outb = (const float*)d_in[16];
    float* out = (float*)d_out;

    float *h, *y, *z, *xr, *wE, *wB, *wC, *wH, *wO, *wOut;
    cudaGetSymbolAddress((void**)&h,    g_h);
    cudaGetSymbolAddress((void**)&y,    g_y);
    cudaGetSymbolAddress((void**)&z,    g_z);
    cudaGetSymbolAddress((void**)&xr,   g_xr);
    cudaGetSymbolAddress((void**)&wE,   g_wE);
    cudaGetSymbolAddress((void**)&wB,   g_wB);
    cudaGetSymbolAddress((void**)&wC,   g_wC);
    cudaGetSymbolAddress((void**)&wH,   g_wH);
    cudaGetSymbolAddress((void**)&wO,   g_wO);
    cudaGetSymbolAddress((void**)&wOut, g_wOut);
    float *stp;
    cudaGetSymbolAddress((void**)&stp,  g_st);
    float *bup;
    cudaGetSymbolAddress((void**)&bup,  g_bu);

    dim3 tb(256);
    const int MB = M_TOT / BM;   // 256

    // ---- prep: tf32-round weights & input (cheap, every call) ----
    round_copy<<<(M_TOT*INDIM)/256, tb>>>(xr, x, M_TOT*INDIM);
    round_copy<<<(HID*INDIM)/256, tb>>>(wE, embW, HID*INDIM);
    round_copy<<<(OUTD*HID)/256, tb>>>(wOut, outW, OUTD*HID);
    round_copy<<<(NLAYERS*MLPD*HID)/256, tb>>>(wH, Wh, NLAYERS*MLPD*HID);
    round_copy<<<(NLAYERS*HID*MLPD)/256, tb>>>(wO, Wo, NLAYERS*HID*MLPD);
    build_bcat<<<(NLAYERS*S2*HID)/256, tb>>>(Bre, Bim);
    build_ccat<<<(NLAYERS*HID*S2)/256, tb>>>(Cre, Cim);

    // embedding: h = rtf(x @ embW^T + embb)
    tgemm_nt<<<dim3(HID/BN, MB), tb>>>(M_TOT, HID, INDIM, xr, wE, embb, nullptr, h, 6);

    for (int l = 0; l < NLAYERS; l++) {
        // Bu (complex, fused): bu = h @ Bcat^T   [M, 512]
        tgemm_nt<<<dim3(S2/BN, MB), tb>>>(M_TOT, S2, HID, h, wB + (size_t)l*S2*HID,
                                          nullptr, nullptr, bup, 0);
        // chunked complex scan (gamma applied in scanA; scanC rounds)
        scanA<<<(BATCHN*NCH*STATEN)/256, tb>>>(nu, th, gl, l);
        scanB<<<(BATCHN*STATEN + 255)/256, tb>>>(nu, th, l);
        scanC<<<(BATCHN*NCH*STATEN)/256, tb>>>(nu, th, l);

        // y = rtf([st_re|st_im] @ [Cre|-Cim]^T + D*h)
        tgemm_nt<<<dim3(HID/BN, MB), tb>>>(M_TOT, HID, S2, stp, wC + (size_t)l*HID*S2,
                                           Dv + (size_t)l*HID, h, y, 7);
        // MLP
        tgemm_nt<<<dim3(MLPD/BN, MB), tb>>>(M_TOT, MLPD, HID, y, wH + (size_t)l*MLPD*HID,
                                            bh + (size_t)l*MLPD, nullptr, z, 2);
        tgemm_nt<<<dim3(HID/BN, MB), tb>>>(M_TOT, HID, MLPD, z, wO + (size_t)l*HID*MLPD,
                                           bo + (size_t)l*HID, y, h, 3);
    }

    // out = h @ outW^T + outb   (no rounding)
    tgemm_nt<<<dim3(OUTD/BN, MB), tb>>>(M_TOT, OUTD, HID, h, wOut, outb, nullptr, out, 1);
}

// round 4
// speedup vs baseline: 2.8594x; 1.0475x over previous
#include <cuda_runtime.h>
#include <math.h>
#include <stdint.h>

#define BATCHN  16
#define SEQL    2048
#define INDIM   64
#define HID     256
#define STATEN  256
#define MLPD    1024
#define OUTD    128
#define NLAYERS 4
#define M_TOT   (BATCHN*SEQL)   /* 32768 */
#define CH      64
#define NCH     (SEQL/CH)       /* 32 */
#define LOG2CH  6
#define S2      (2*STATEN)      /* 512 */

// ---------------- scratch (static device globals) ---------------------------
__device__ float g_h  [M_TOT*HID];
__device__ float g_y  [M_TOT*HID];
__device__ float g_bu [M_TOT*S2];       // [M, 512]: cols 0-255 re, 256-511 im
__device__ float g_st [M_TOT*S2];
__device__ float g_z  [M_TOT*MLPD];
// pre-rounded (tf32-valued) weights / input
__device__ float g_xr  [M_TOT*INDIM];
__device__ float g_wE  [HID*INDIM];
__device__ float g_wB  [NLAYERS*S2*HID];     // [l][512][256] : Bre stacked on Bim
__device__ float g_wC  [NLAYERS*HID*S2];     // [l][256][512] : [Cre | -Cim]
__device__ float g_wH  [NLAYERS*MLPD*HID];
__device__ float g_wO  [NLAYERS*HID*MLPD];
__device__ float g_wOut[OUTD*HID];

__device__ __forceinline__ float rtf(float x){
    uint32_t r; asm("cvt.rna.tf32.f32 %0, %1;" : "=r"(r) : "f"(x));
    return __uint_as_float(r);
}

// ==================== TF32 tensor-core GEMM =================================
// C[M,N] = epi(A[M,K] @ W[N,K]^T)   (A, W already tf32-valued)
// epi: 1 = store acc + bias            (final output, no rounding)
//      2 = store rtf(gelu(acc+bias))
//      3 = store rtf(acc+bias+resid)
//      0 = store raw
//      6 = store rtf(acc+bias)
//      7 = store rtf(acc + bias[c]*resid)   (bias slot carries D vector)
#define BM   128
#define BK   16
#define ASTR 20
#define NSTG 3

__device__ __forceinline__ void cp16(uint32_t dst, const float* src){
    asm volatile("cp.async.ca.shared.global [%0], [%1], 16;\n" :: "r"(dst), "l"(src));
}
__device__ __forceinline__ void mma_tf32(float* c, const uint32_t* a, const uint32_t* b){
    asm volatile("mma.sync.aligned.m16n8k8.row.col.f32.tf32.tf32.f32 "
        "{%0,%1,%2,%3}, {%4,%5,%6,%7}, {%8,%9}, {%0,%1,%2,%3};"
        : "+f"(c[0]), "+f"(c[1]), "+f"(c[2]), "+f"(c[3])
        : "r"(a[0]), "r"(a[1]), "r"(a[2]), "r"(a[3]), "r"(b[0]), "r"(b[1]));
}

template<int BNt>
__global__ __launch_bounds__(256)
void tgemm(int M, int N, int K,
           const float* __restrict__ A, const float* __restrict__ W,
           const float* __restrict__ bias, const float* __restrict__ resid,
           float* __restrict__ C, int epi)
{
    constexpr int NT    = BNt/32;          // n-fragments per warp (4 or 8)
    constexpr int NLB   = BNt/128;         // B row-chunks per thread
    constexpr int SLOTA = BM*ASTR;
    constexpr int SLOTB = BNt*ASTR;

    extern __shared__ __align__(16) float smem[];
    float* As = smem;                      // NSTG * SLOTA
    float* Bs = smem + NSTG*SLOTA;         // NSTG * SLOTB

    int tid  = threadIdx.x;
    int lane = tid & 31;
    int wid  = tid >> 5;
    int gr   = lane >> 2;
    int ct   = lane & 3;
    int wm   = (wid >> 2) * 64;
    int wn   = (wid & 3) * (BNt/4);
    int row0 = blockIdx.y * BM;
    int col0 = blockIdx.x * BNt;

    int lrow = tid >> 1;
    int loff = (tid & 1) * 8;
    const float* Ag = A + (size_t)(row0 + lrow) * K + loff;
    const float* Wg = W + (size_t)(col0 + lrow) * K + loff;
    uint32_t sAb = (uint32_t)__cvta_generic_to_shared(&As[lrow*ASTR + loff]);
    uint32_t sBb = (uint32_t)__cvta_generic_to_shared(&Bs[lrow*ASTR + loff]);

    float acc[4][NT][4];
    #pragma unroll
    for (int i=0;i<4;i++)
        #pragma unroll
        for (int j=0;j<NT;j++)
            #pragma unroll
            for (int q=0;q<4;q++) acc[i][j][q] = 0.f;

    int nk = K / BK;

    auto load_stage = [&](int kt){
        int slot = kt % NSTG;
        int k0 = kt * BK;
        cp16(sAb + slot*SLOTA*4,      Ag + k0);
        cp16(sAb + slot*SLOTA*4 + 16, Ag + k0 + 4);
        #pragma unroll
        for (int r = 0; r < NLB; r++) {
            uint32_t d = sBb + slot*SLOTB*4 + r*128*ASTR*4;
            const float* s = Wg + (size_t)r*128*K + k0;
            cp16(d, s); cp16(d + 16, s + 4);
        }
        asm volatile("cp.async.commit_group;\n");
    };

    load_stage(0);
    load_stage(1);

    for (int kt = 0; kt < nk; kt++) {
        asm volatile("cp.async.wait_group 1;\n");
        __syncthreads();
        if (kt + 2 < nk) load_stage(kt + 2);
        else             asm volatile("cp.async.commit_group;\n");

        int slot = kt % NSTG;
        const uint32_t* Asm = (const uint32_t*)&As[slot*SLOTA];
        const uint32_t* Bsm = (const uint32_t*)&Bs[slot*SLOTB];
        #pragma unroll
        for (int ks = 0; ks < 2; ks++) {
            int kk = ks*8 + ct;
            uint32_t ua[4][4], ub[NT][2];
            #pragma unroll
            for (int mt = 0; mt < 4; mt++) {
                int r = wm + mt*16 + gr;
                ua[mt][0] = Asm[ r      *ASTR + kk    ];
                ua[mt][1] = Asm[(r + 8)*ASTR + kk    ];
                ua[mt][2] = Asm[ r      *ASTR + kk + 4];
                ua[mt][3] = Asm[(r + 8)*ASTR + kk + 4];
            }
            #pragma unroll
            for (int nt = 0; nt < NT; nt++) {
                int n = wn + nt*8 + gr;
                ub[nt][0] = Bsm[n*ASTR + kk    ];
                ub[nt][1] = Bsm[n*ASTR + kk + 4];
            }
            #pragma unroll
            for (int mt = 0; mt < 4; mt++)
                #pragma unroll
                for (int nt = 0; nt < NT; nt++)
                    mma_tf32(acc[mt][nt], ua[mt], ub[nt]);
        }
    }

    #pragma unroll
    for (int mt = 0; mt < 4; mt++) {
        #pragma unroll
        for (int half = 0; half < 2; half++) {
            int r = row0 + wm + mt*16 + gr + half*8;
            size_t ro = (size_t)r * N;
            #pragma unroll
            for (int nt = 0; nt < NT; nt++) {
                int cc = col0 + wn + nt*8 + ct*2;
                float v0 = acc[mt][nt][half*2 + 0];
                float v1 = acc[mt][nt][half*2 + 1];
                if (epi == 0) {
                    C[ro + cc]     = v0;
                    C[ro + cc + 1] = v1;
                } else if (epi == 1) {
                    C[ro + cc]     = v0 + bias[cc];
                    C[ro + cc + 1] = v1 + bias[cc + 1];
                } else if (epi == 2) {
                    float t0 = v0 + bias[cc];
                    float t1 = v1 + bias[cc + 1];
                    C[ro + cc]     = rtf(0.5f * t0 * (1.0f + erff(t0 * 0.70710678118654752f)));
                    C[ro + cc + 1] = rtf(0.5f * t1 * (1.0f + erff(t1 * 0.70710678118654752f)));
                } else if (epi == 3) {
                    C[ro + cc]     = rtf(v0 + bias[cc]     + resid[ro + cc]);
                    C[ro + cc + 1] = rtf(v1 + bias[cc + 1] + resid[ro + cc + 1]);
                } else if (epi == 6) {
                    C[ro + cc]     = rtf(v0 + bias[cc]);
                    C[ro + cc + 1] = rtf(v1 + bias[cc + 1]);
                } else { // 7
                    C[ro + cc]     = rtf(v0 + bias[cc]     * resid[ro + cc]);
                    C[ro + cc + 1] = rtf(v1 + bias[cc + 1] * resid[ro + cc + 1]);
                }
            }
        }
    }
}

// ==================== weight prep (tf32 rounding / concat) ==================
__global__ void round_copy4(float4* __restrict__ dst, const float4* __restrict__ src, int n4)
{
    int i = blockIdx.x * blockDim.x + threadIdx.x;
    if (i < n4) {
        float4 v = src[i];
        v.x = rtf(v.x); v.y = rtf(v.y); v.z = rtf(v.z); v.w = rtf(v.w);
        dst[i] = v;
    }
}
__global__ void build_bcat(const float* __restrict__ Bre, const float* __restrict__ Bim)
{
    int i = blockIdx.x * blockDim.x + threadIdx.x;     // NLAYERS*512*256
    int k = i & (HID-1);
    int row = (i >> 8) & (S2-1);
    int l = i >> 17;
    float v = (row < STATEN) ? Bre[((size_t)l*STATEN + row)*HID + k]
                             : Bim[((size_t)l*STATEN + row - STATEN)*HID + k];
    g_wB[i] = rtf(v);
}
__global__ void build_ccat(const float* __restrict__ Cre, const float* __restrict__ Cim)
{
    int i = blockIdx.x * blockDim.x + threadIdx.x;     // NLAYERS*256*512
    int k = i & (S2-1);
    int hh = (i >> 9) & (HID-1);
    int l = i >> 17;
    float v = (k < STATEN) ?  Cre[((size_t)l*HID + hh)*STATEN + k]
                           : -Cim[((size_t)l*HID + hh)*STATEN + k - STATEN];
    g_wC[i] = rtf(v);
}

// ==================== fused LRU scan (one kernel per layer) ================
__device__ __forceinline__ void lam_of(const float* nu_log, const float* th_log,
                                       int layer, int s, float& lre, float& lim)
{
    float nu = nu_log[layer*STATEN + s];
    float th = th_log[layer*STATEN + s];
    float mag = expf(-expf(nu));
    float ang = expf(th);
    float sv, cv;
    sincosf(ang, &sv, &cv);
    lre = mag * cv;
    lim = mag * sv;
}

// grid: (STATEN/32, BATCHN), block: 1024 = 32 chunks x 32 states
__global__ __launch_bounds__(1024)
void scan_fused(const float* __restrict__ nu_log, const float* __restrict__ th_log,
                const float* __restrict__ gl_log, int layer)
{
    __shared__ float se_r[NCH][32], se_i[NCH][32];
    __shared__ float ca_r[NCH][32], ca_i[NCH][32];

    int tid = threadIdx.x;
    int c   = tid >> 5;          // chunk 0..31
    int sl  = tid & 31;          // state lane
    int s   = blockIdx.x * 32 + sl;
    int b   = blockIdx.y;

    float lre, lim;
    lam_of(nu_log, th_log, layer, s, lre, lim);
    float ga = expf(gl_log[layer*STATEN + s]);

    size_t base = ((size_t)b * SEQL + (size_t)c * CH) * S2 + s;

    // phase 1: local scan, keep only chunk-end
    {
        float sr = 0.f, si = 0.f;
        #pragma unroll 4
        for (int t = 0; t < CH; t++) {
            size_t o = base + (size_t)t * S2;
            float br = g_bu[o]          * ga;
            float bi = g_bu[o + STATEN] * ga;
            float nr = fmaf(lre, sr, fmaf(-lim, si, br));
            float ni = fmaf(lre, si, fmaf( lim, sr, bi));
            sr = nr; si = ni;
        }
        se_r[c][sl] = sr; se_i[c][sl] = si;
    }
    __syncthreads();

    // phase 2: serial carry combine (warp 0 only)
    if (tid < 32) {
        float ar = lre, ai = lim;    // lam^CH
        #pragma unroll
        for (int q = 0; q < LOG2CH; q++) {
            float nr = ar*ar - ai*ai;
            ai = 2.f * ar * ai;
            ar = nr;
        }
        float cr = 0.f, ci = 0.f;
        #pragma unroll
        for (int c2 = 0; c2 < NCH; c2++) {
            ca_r[c2][sl] = cr; ca_i[c2][sl] = ci;
            float er = se_r[c2][sl], ei = se_i[c2][sl];
            float nr = fmaf(ar, cr, fmaf(-ai, ci, er));
            float ni = fmaf(ar, ci, fmaf( ai, cr, ei));
            cr = nr; ci = ni;
        }
    }
    __syncthreads();

    // phase 3: rescan with carry-in, write rounded states
    {
        float sr = ca_r[c][sl], si = ca_i[c][sl];
        #pragma unroll 4
        for (int t = 0; t < CH; t++) {
            size_t o = base + (size_t)t * S2;
            float br = g_bu[o]          * ga;
            float bi = g_bu[o + STATEN] * ga;
            float nr = fmaf(lre, sr, fmaf(-lim, si, br));
            float ni = fmaf(lre, si, fmaf( lim, sr, bi));
            sr = nr; si = ni;
            g_st[o]          = rtf(sr);
            g_st[o + STATEN] = rtf(si);
        }
    }
}

// ==================== driver ================================================
extern "C" void kernel_launch(void* const* d_in, const int* in_sizes, int n_in,
                              void* d_out, int out_size)
{
    (void)in_sizes; (void)n_in; (void)out_size;
    const float* x    = (const float*)d_in[0];
    const float* embW = (const float*)d_in[1];
    const float* embb = (const float*)d_in[2];
    const float* nu   = (const float*)d_in[3];
    const float* th   = (const float*)d_in[4];
    const float* gl   = (const float*)d_in[5];
    const float* Bre  = (const float*)d_in[6];
    const float* Bim  = (const float*)d_in[7];
    const float* Cre  = (const float*)d_in[8];
    const float* Cim  = (const float*)d_in[9];
    const float* Dv   = (const float*)d_in[10];
    const float* Wh   = (const float*)d_in[11];
    const float* bh   = (const float*)d_in[12];
    const float* Wo   = (const float*)d_in[13];
    const float* bo   = (const float*)d_in[14];
    const float* outW = (const float*)d_in[15];
    const float* outb = (const float*)d_in[16];
    float* out = (float*)d_out;

    float *h, *y, *z, *xr, *wE, *wB, *wC, *wH, *wO, *wOut, *stp, *bup;
    cudaGetSymbolAddress((void**)&h,    g_h);
    cudaGetSymbolAddress((void**)&y,    g_y);
    cudaGetSymbolAddress((void**)&z,    g_z);
    cudaGetSymbolAddress((void**)&xr,   g_xr);
    cudaGetSymbolAddress((void**)&wE,   g_wE);
    cudaGetSymbolAddress((void**)&wB,   g_wB);
    cudaGetSymbolAddress((void**)&wC,   g_wC);
    cudaGetSymbolAddress((void**)&wH,   g_wH);
    cudaGetSymbolAddress((void**)&wO,   g_wO);
    cudaGetSymbolAddress((void**)&wOut, g_wOut);
    cudaGetSymbolAddress((void**)&stp,  g_st);
    cudaGetSymbolAddress((void**)&bup,  g_bu);

    const int SM128 = NSTG*(BM+128)*ASTR*4;   // 61440
    const int SM256 = NSTG*(BM+256)*ASTR*4;   // 92160
    cudaFuncSetAttribute(tgemm<128>, cudaFuncAttributeMaxDynamicSharedMemorySize, SM128);
    cudaFuncSetAttribute(tgemm<256>, cudaFuncAttributeMaxDynamicSharedMemorySize, SM256);

    dim3 tb(256);
    const int MB = M_TOT / BM;   // 256

    // ---- prep: tf32-round weights & input ----
    round_copy4<<<(M_TOT*INDIM/4+255)/256, tb>>>((float4*)xr, (const float4*)x, M_TOT*INDIM/4);
    round_copy4<<<(HID*INDIM/4+255)/256, tb>>>((float4*)wE, (const float4*)embW, HID*INDIM/4);
    round_copy4<<<(OUTD*HID/4+255)/256, tb>>>((float4*)wOut, (const float4*)outW, OUTD*HID/4);
    round_copy4<<<(NLAYERS*MLPD*HID/4+255)/256, tb>>>((float4*)wH, (const float4*)Wh, NLAYERS*MLPD*HID/4);
    round_copy4<<<(NLAYERS*HID*MLPD/4+255)/256, tb>>>((float4*)wO, (const float4*)Wo, NLAYERS*HID*MLPD/4);
    build_bcat<<<(NLAYERS*S2*HID)/256, tb>>>(Bre, Bim);
    build_ccat<<<(NLAYERS*HID*S2)/256, tb>>>(Cre, Cim);

    // embedding: h = rtf(x @ embW^T + embb)
    tgemm<256><<<dim3(HID/256, MB), tb, SM256>>>(M_TOT, HID, INDIM, xr, wE, embb, nullptr, h, 6);

    for (int l = 0; l < NLAYERS; l++) {
        // Bu (complex, fused): bu = h @ Bcat^T   [M, 512]
        tgemm<256><<<dim3(S2/256, MB), tb, SM256>>>(M_TOT, S2, HID, h, wB + (size_t)l*S2*HID,
                                                    nullptr, nullptr, bup, 0);
        // fused chunked complex scan
        scan_fused<<<dim3(STATEN/32, BATCHN), 1024>>>(nu, th, gl, l);

        // y = rtf([st_re|st_im] @ [Cre|-Cim]^T + D*h)
        tgemm<256><<<dim3(HID/256, MB), tb, SM256>>>(M_TOT, HID, S2, stp, wC + (size_t)l*HID*S2,
                                                     Dv + (size_t)l*HID, h, y, 7);
        // MLP
        tgemm<256><<<dim3(MLPD/256, MB), tb, SM256>>>(M_TOT, MLPD, HID, y, wH + (size_t)l*MLPD*HID,
                                                      bh + (size_t)l*MLPD, nullptr, z, 2);
        tgemm<256><<<dim3(HID/256, MB), tb, SM256>>>(M_TOT, HID, MLPD, z, wO + (size_t)l*HID*MLPD,
                                                     bo + (size_t)l*HID, y, h, 3);
    }

    // out = h @ outW^T + outb   (no rounding)
    tgemm<128><<<dim3(OUTD/128, MB), tb, SM128>>>(M_TOT, OUTD, HID, h, wOut, outb, nullptr, out, 1);
}